// round 12
// baseline (speedup 1.0000x reference)
#include <cuda_runtime.h>
#include <cuda_fp16.h>
#include <cstdint>

// ============================================================================
// DQSN collapsed: out = A @ w2' + b2*(1-2^-16)
//   A[b,j] = sum_t spike_t(h_in[b,j]) * 2^(t-17),  h_in = x@w1' + b1
// GEMM1: fp16 mma, logical K-tripling [xh|xh|xl]x[wh|wl|wh] (K'=768)
// GEMM2: single-product fp16 Ah @ wh' (K=1024); dropped terms ~2.4e-4 rel
//   (calibrated R9/R10). Near-threshold IF elements (|v-1|<1e-4) recomputed
//   in-CTA with sequential fp32 FMA (reference rounding).
// R12 = R11 with the stage-index bug fixed: current compute slot is kt%3
//   (R11 read the slot being loaded for kt+1 -> NaN).
// ============================================================================

#define MDIM 8192
#define IDIM 256
#define HDIM 1024
#define ODIM 256

#define G1_NK 12            // K'=768 in BK=64 tiles
#define G2_NK 16            // K=1024 in BK=64 tiles
#define STRIDE 72           // halves per smem row (144B, ldmatrix conflict-free)
#define G1_STAGE (256 * STRIDE)               // halves: 128 A + 128 B rows
#define G2_STAGE (192 * STRIDE)               // halves: 128 A + 64 W rows
#define G1_SMEM (3 * G1_STAGE * 2)            // 110592 B
#define G2_SMEM (3 * G2_STAGE * 2)            // 82944 B
#define FIX_CAP 2048
#define DELTA 1e-4f

// --------------------------- global scratch (no allocs) ---------------------
__device__ __align__(16) __half g_xh [(size_t)MDIM * IDIM];
__device__ __align__(16) __half g_xl [(size_t)MDIM * IDIM];
__device__ __align__(16) __half g_w1h[(size_t)HDIM * IDIM];
__device__ __align__(16) __half g_w1l[(size_t)HDIM * IDIM];
__device__ __align__(16) __half g_w2h[(size_t)ODIM * HDIM];
__device__ __align__(16) __half g_Ah [(size_t)MDIM * HDIM];

// --------------------------- helpers ----------------------------------------
__device__ __forceinline__ void cp16(uint32_t s, const void* g) {
    asm volatile("cp.async.cg.shared.global [%0], [%1], 16;" :: "r"(s), "l"(g));
}
#define CP_COMMIT() asm volatile("cp.async.commit_group;" ::: "memory")
#define CP_WAIT1()  asm volatile("cp.async.wait_group 1;" ::: "memory")

__device__ __forceinline__ void ldm_x4(uint32_t* r, uint32_t addr) {
    asm volatile("ldmatrix.sync.aligned.m8n8.x4.shared.b16 {%0,%1,%2,%3}, [%4];"
        : "=r"(r[0]), "=r"(r[1]), "=r"(r[2]), "=r"(r[3]) : "r"(addr));
}
__device__ __forceinline__ void mma_f16(float* c, const uint32_t* a, const uint32_t* b) {
    asm volatile(
        "mma.sync.aligned.m16n8k16.row.col.f32.f16.f16.f32 "
        "{%0,%1,%2,%3}, {%4,%5,%6,%7}, {%8,%9}, {%0,%1,%2,%3};"
        : "+f"(c[0]), "+f"(c[1]), "+f"(c[2]), "+f"(c[3])
        : "r"(a[0]), "r"(a[1]), "r"(a[2]), "r"(a[3]), "r"(b[0]), "r"(b[1]));
}
__device__ __forceinline__ uint32_t pack_h2(float a, float b) {
    __half2 t = __floats2half2_rn(a, b);
    return *reinterpret_cast<uint32_t*>(&t);
}

// IF neuron closed-form sim
__device__ __forceinline__ float if_sim(float h) {
    float v = 0.0f, av = 0.0f, coef = 0x1p-16f;
#pragma unroll
    for (int t = 0; t < 16; t++) {
        v += h;
        const bool s = (v >= 1.0f);
        av = s ? (av + coef) : av;
        v = s ? 0.0f : v;
        coef += coef;
    }
    return av;
}
__device__ __forceinline__ float if_sim_flag(float h, bool& near) {
    float v = 0.0f, av = 0.0f, coef = 0x1p-16f;
#pragma unroll
    for (int t = 0; t < 16; t++) {
        v += h;
        near |= (fabsf(v - 1.0f) < DELTA);
        const bool s = (v >= 1.0f);
        av = s ? (av + coef) : av;
        v = s ? 0.0f : v;
        coef += coef;
    }
    return av;
}

// --------------------------- fused converter (4 floats/thread) ---------------
#define CONV_Q1 (MDIM * IDIM / 4)
#define CONV_Q2 (HDIM * IDIM / 4)
#define CONV_Q3 (ODIM * HDIM / 4)
#define CONV_QTOTAL (CONV_Q1 + CONV_Q2 + CONV_Q3)

__global__ __launch_bounds__(256)
void conv_all_kernel(const float* __restrict__ x, const float* __restrict__ w1,
                     const float* __restrict__ w2,
                     __half* __restrict__ xh, __half* __restrict__ xl,
                     __half* __restrict__ w1h, __half* __restrict__ w1l,
                     __half* __restrict__ w2h)
{
    const int i = blockIdx.x * blockDim.x + threadIdx.x;   // quad index
    if (i < CONV_Q1 + CONV_Q2) {
        const float* src;
        __half *dhi, *dlo;
        int idx;
        if (i < CONV_Q1) { src = x;  dhi = xh;  dlo = xl;  idx = i; }
        else             { src = w1; dhi = w1h; dlo = w1l; idx = i - CONV_Q1; }
        const float4 v = *reinterpret_cast<const float4*>(src + (size_t)idx * 4);
        const __half h0 = __float2half_rn(v.x), h1 = __float2half_rn(v.y);
        const __half h2 = __float2half_rn(v.z), h3 = __float2half_rn(v.w);
        uint2 hu, lu;
        hu.x = pack_h2(__half2float(h0), __half2float(h1));
        hu.y = pack_h2(__half2float(h2), __half2float(h3));
        lu.x = pack_h2(v.x - __half2float(h0), v.y - __half2float(h1));
        lu.y = pack_h2(v.z - __half2float(h2), v.w - __half2float(h3));
        reinterpret_cast<uint2*>(dhi)[idx] = hu;
        reinterpret_cast<uint2*>(dlo)[idx] = lu;
    } else {
        const int idx = i - CONV_Q1 - CONV_Q2;             // w2: hi only
        const float4 v = *reinterpret_cast<const float4*>(w2 + (size_t)idx * 4);
        uint2 hu;
        hu.x = pack_h2(v.x, v.y);
        hu.y = pack_h2(v.z, v.w);
        reinterpret_cast<uint2*>(w2h)[idx] = hu;
    }
}

// --------------------------- GEMM1: fp16, 128x128, BK=64, 3-stage -----------
// C = [xh|xh|xl] @ [wh|wl|wh]' (K'=768), epilogue: +b1, IF sim (+flag),
// write Ah row-major; in-CTA fixup of near-threshold elements.
__global__ __launch_bounds__(256, 1)
void gemm1_f16(const __half* __restrict__ Xh, const __half* __restrict__ Xl,
               const __half* __restrict__ Wh, const __half* __restrict__ Wl,
               const float* __restrict__ bias, __half* __restrict__ Ah,
               const float* __restrict__ xf, const float* __restrict__ w1f)
{
    extern __shared__ __half sm[];                  // 3 * G1_STAGE halves
    __shared__ int s_cnt;
    __shared__ uint32_t s_list[FIX_CAP];
    const uint32_t smb = (uint32_t)__cvta_generic_to_shared(sm);

    const int tid = threadIdx.x;
    const int lane = tid & 31;
    const int wid = tid >> 5;
    const int g = lane >> 3, lr = lane & 7;
    const int wm = (wid & 1) * 64, wn = (wid >> 1) * 32;
    const int mblk = blockIdx.y, nblk = blockIdx.x;

    if (tid == 0) s_cnt = 0;

    int a_off[4], b_off[2];
#pragma unroll
    for (int ma = 0; ma < 4; ma++)
        a_off[ma] = (wm + ma * 16 + (g & 1) * 8 + lr) * STRIDE + (g >> 1) * 8;
#pragma unroll
    for (int nb = 0; nb < 2; nb++)
        b_off[nb] = (128 + wn + nb * 16 + (g >> 1) * 8 + lr) * STRIDE + (g & 1) * 8;

    float acc[4][4][4];
#pragma unroll
    for (int i = 0; i < 4; i++)
#pragma unroll
        for (int j = 0; j < 4; j++)
#pragma unroll
            for (int k = 0; k < 4; k++) acc[i][j][k] = 0.0f;

    // logical K-tripling: region 0:[xh,wh] 1:[xh,wl] 2:[xl,wh]
    auto load_stage = [&](int s, int kt) {
        const int k0 = kt * 64;
        const int region = k0 >> 8;
        const int koff = k0 & 255;
        const __half* Asrc = (region < 2) ? Xh : Xl;
        const __half* Bsrc = (region == 1) ? Wl : Wh;
#pragma unroll
        for (int i = 0; i < 8; i++) {
            const int c = tid + i * 256;
            const int row = c >> 3, ch = (c & 7) * 8;   // halves
            const __half* gp;
            if (row < 128)
                gp = Asrc + (size_t)(mblk * 128 + row) * IDIM + koff + ch;
            else
                gp = Bsrc + (size_t)(nblk * 128 + (row - 128)) * IDIM + koff + ch;
            cp16(smb + (uint32_t)(s * G1_STAGE + row * STRIDE + ch) * 2, gp);
        }
    };

    auto load_frags = [&](uint32_t stg, int kk, uint32_t a[4][4], uint32_t b[4][2]) {
#pragma unroll
        for (int ma = 0; ma < 4; ma++)
            ldm_x4(a[ma], stg + (uint32_t)(a_off[ma] + kk) * 2);
#pragma unroll
        for (int nb = 0; nb < 2; nb++) {
            uint32_t r[4];
            ldm_x4(r, stg + (uint32_t)(b_off[nb] + kk) * 2);
            b[2 * nb][0] = r[0]; b[2 * nb][1] = r[1];
            b[2 * nb + 1][0] = r[2]; b[2 * nb + 1][1] = r[3];
        }
    };

    load_stage(0, 0); CP_COMMIT();
    load_stage(1, 1); CP_COMMIT();
    int s_cur = 0, s_pre = 2;   // slot holding tile kt; slot to prefetch kt+2
    for (int kt = 0; kt < G1_NK; kt++) {
        CP_WAIT1();            // tile kt complete (kt+1 may be in flight)
        __syncthreads();
        if (kt + 2 < G1_NK) load_stage(s_pre, kt + 2);
        CP_COMMIT();           // overlaps the compute below (2-tile slack)
        const uint32_t stg = smb + (uint32_t)(s_cur * G1_STAGE) * 2;
        if (++s_pre == 3) s_pre = 0;
        if (++s_cur == 3) s_cur = 0;

        uint32_t aF[2][4][4], bF[2][4][2];
        load_frags(stg, 0, aF[0], bF[0]);
#pragma unroll
        for (int kk = 0; kk < 4; kk++) {
            if (kk < 3) load_frags(stg, (kk + 1) * 16, aF[(kk + 1) & 1], bF[(kk + 1) & 1]);
#pragma unroll
            for (int ma = 0; ma < 4; ma++)
#pragma unroll
                for (int na = 0; na < 4; na++)
                    mma_f16(acc[ma][na], aF[kk & 1][ma], bF[kk & 1][na]);
        }
    }

    // epilogue: +bias, IF sim + flag (smem list), write Ah
    const int gq = lane >> 2, tq = lane & 3;
#pragma unroll
    for (int na = 0; na < 4; na++) {
        const int col = nblk * 128 + wn + na * 8 + 2 * tq;
        const float bb0 = __ldg(bias + col);
        const float bb1 = __ldg(bias + col + 1);
#pragma unroll
        for (int ma = 0; ma < 4; ma++) {
            const int row0 = mblk * 128 + wm + ma * 16 + gq;
#pragma unroll
            for (int rv = 0; rv < 2; rv++) {
                const int row = row0 + rv * 8;
                bool f0 = false, f1 = false;
                const float a0 = if_sim_flag(acc[ma][na][rv * 2 + 0] + bb0, f0);
                const float a1 = if_sim_flag(acc[ma][na][rv * 2 + 1] + bb1, f1);
                const size_t pidx = (size_t)row * (HDIM / 2) + (col >> 1);
                reinterpret_cast<uint32_t*>(Ah)[pidx] = pack_h2(a0, a1);
                if (f0) {
                    const int idx = atomicAdd(&s_cnt, 1);
                    if (idx < FIX_CAP) s_list[idx] = (uint32_t)(row * 1024 + col);
                }
                if (f1) {
                    const int idx = atomicAdd(&s_cnt, 1);
                    if (idx < FIX_CAP) s_list[idx] = (uint32_t)(row * 1024 + col + 1);
                }
            }
        }
    }

    // In-CTA fixup with sequential ascending-k fp32 FMA (reference rounding).
    __syncthreads();
    int n = s_cnt;
    n = n < FIX_CAP ? n : FIX_CAP;
    for (int i = tid; i < n; i += 256) {
        const uint32_t code = s_list[i];
        const int m = code >> 10, j = code & 1023;
        const float* xr = xf + (size_t)m * IDIM;
        const float* wr = w1f + (size_t)j * IDIM;
        float accs = 0.0f;
        for (int k = 0; k < IDIM; k++) accs = fmaf(xr[k], wr[k], accs);
        const float a = if_sim(accs + __ldg(bias + j));
        Ah[(size_t)m * HDIM + j] = __float2half_rn(a);
    }
}

// --------------------------- GEMM2: fp16, 128x64, BK=64, 3-stage ------------
// out = Ah @ wh' (K=1024), + b2*(1-2^-16), fp32 row-major [., 256].
// Stage rows: [0,128) Ah, [128,192) Wh.
__global__ __launch_bounds__(256, 1)
void gemm2_f16(const __half* __restrict__ Ahg, const __half* __restrict__ Wh,
               const float* __restrict__ bias, float* __restrict__ out)
{
    extern __shared__ __half sm[];                  // 3 * G2_STAGE halves
    const uint32_t smb = (uint32_t)__cvta_generic_to_shared(sm);

    const int tid = threadIdx.x;
    const int lane = tid & 31;
    const int wid = tid >> 5;
    const int g = lane >> 3, lr = lane & 7;
    const int wm = (wid & 1) * 64, wn = (wid >> 1) * 16;
    const int mblk = blockIdx.y, nblk = blockIdx.x;

    int a_off[4];
#pragma unroll
    for (int ma = 0; ma < 4; ma++)
        a_off[ma] = (wm + ma * 16 + (g & 1) * 8 + lr) * STRIDE + (g >> 1) * 8;
    const int b_off = (128 + wn + (g >> 1) * 8 + lr) * STRIDE + (g & 1) * 8;

    float acc[4][2][4];
#pragma unroll
    for (int i = 0; i < 4; i++)
#pragma unroll
        for (int j = 0; j < 2; j++)
#pragma unroll
            for (int k = 0; k < 4; k++) acc[i][j][k] = 0.0f;

    auto load_stage = [&](int s, int kt) {
        const int k0 = kt * 64;
#pragma unroll
        for (int i = 0; i < 6; i++) {
            const int c = tid + i * 256;
            const int row = c >> 3, ch = (c & 7) * 8;
            const __half* gp;
            if (row < 128)
                gp = Ahg + (size_t)(mblk * 128 + row) * HDIM + k0 + ch;
            else
                gp = Wh + (size_t)(nblk * 64 + (row - 128)) * HDIM + k0 + ch;
            cp16(smb + (uint32_t)(s * G2_STAGE + row * STRIDE + ch) * 2, gp);
        }
    };

    auto load_frags = [&](uint32_t stg, int kk, uint32_t a[4][4], uint32_t b[2][2]) {
#pragma unroll
        for (int ma = 0; ma < 4; ma++)
            ldm_x4(a[ma], stg + (uint32_t)(a_off[ma] + kk) * 2);
        uint32_t r[4];
        ldm_x4(r, stg + (uint32_t)(b_off + kk) * 2);
        b[0][0] = r[0]; b[0][1] = r[1];
        b[1][0] = r[2]; b[1][1] = r[3];
    };

    load_stage(0, 0); CP_COMMIT();
    load_stage(1, 1); CP_COMMIT();
    int s_cur = 0, s_pre = 2;
    for (int kt = 0; kt < G2_NK; kt++) {
        CP_WAIT1();
        __syncthreads();
        if (kt + 2 < G2_NK) load_stage(s_pre, kt + 2);
        CP_COMMIT();
        const uint32_t stg = smb + (uint32_t)(s_cur * G2_STAGE) * 2;
        if (++s_pre == 3) s_pre = 0;
        if (++s_cur == 3) s_cur = 0;

        uint32_t aF[2][4][4], bF[2][2][2];
        load_frags(stg, 0, aF[0], bF[0]);
#pragma unroll
        for (int kk = 0; kk < 4; kk++) {
            if (kk < 3) load_frags(stg, (kk + 1) * 16, aF[(kk + 1) & 1], bF[(kk + 1) & 1]);
#pragma unroll
            for (int ma = 0; ma < 4; ma++)
#pragma unroll
                for (int na = 0; na < 2; na++)
                    mma_f16(acc[ma][na], aF[kk & 1][ma], bF[kk & 1][na]);
        }
    }

    const float BSCALE = 1.0f - 0x1p-16f;
    const int gq = lane >> 2, tq = lane & 3;
#pragma unroll
    for (int na = 0; na < 2; na++) {
        const int col = nblk * 64 + wn + na * 8 + 2 * tq;
        const float bb0 = __ldg(bias + col) * BSCALE;
        const float bb1 = __ldg(bias + col + 1) * BSCALE;
#pragma unroll
        for (int ma = 0; ma < 4; ma++) {
            const int row0 = mblk * 128 + wm + ma * 16 + gq;
            *reinterpret_cast<float2*>(out + (size_t)row0 * ODIM + col) =
                make_float2(acc[ma][na][0] + bb0, acc[ma][na][1] + bb1);
            *reinterpret_cast<float2*>(out + (size_t)(row0 + 8) * ODIM + col) =
                make_float2(acc[ma][na][2] + bb0, acc[ma][na][3] + bb1);
        }
    }
}

// --------------------------- launch -----------------------------------------
extern "C" void kernel_launch(void* const* d_in, const int* in_sizes, int n_in,
                              void* d_out, int out_size)
{
    const float* x  = (const float*)d_in[0];   // [8192, 256]
    const float* w1 = (const float*)d_in[1];   // [1024, 256]
    const float* b1 = (const float*)d_in[2];   // [1024]
    const float* w2 = (const float*)d_in[3];   // [256, 1024]
    const float* b2 = (const float*)d_in[4];   // [256]
    float* out = (float*)d_out;                // [8192, 256]

    __half *xh, *xl, *w1h, *w1l, *w2h, *Ah;
    cudaGetSymbolAddress((void**)&xh,  g_xh);
    cudaGetSymbolAddress((void**)&xl,  g_xl);
    cudaGetSymbolAddress((void**)&w1h, g_w1h);
    cudaGetSymbolAddress((void**)&w1l, g_w1l);
    cudaGetSymbolAddress((void**)&w2h, g_w2h);
    cudaGetSymbolAddress((void**)&Ah,  g_Ah);

    cudaFuncSetAttribute(gemm1_f16,
                         cudaFuncAttributeMaxDynamicSharedMemorySize, G1_SMEM);
    cudaFuncSetAttribute(gemm2_f16,
                         cudaFuncAttributeMaxDynamicSharedMemorySize, G2_SMEM);

    conv_all_kernel<<<CONV_QTOTAL / 256, 256>>>(x, w1, w2, xh, xl, w1h, w1l, w2h);

    gemm1_f16<<<dim3(HDIM / 128, MDIM / 128), 256, G1_SMEM>>>(
        xh, xl, w1h, w1l, b1, Ah, x, w1);

    gemm2_f16<<<dim3(ODIM / 64, MDIM / 128), 256, G2_SMEM>>>(
        Ah, w2h, b2, out);
}